// round 8
// baseline (speedup 1.0000x reference)
#include <cuda_runtime.h>
#include <cuda_fp16.h>

// Problem constants (fixed by reference)
#define VOCAB      32000
#define EMBED_DIM  128
#define BATCH      32
#define MAX_TREES  512
#define NSEG       (BATCH * MAX_TREES)   // 16384

// Scratch (allocation-free __device__ globals)
__device__ int g_seg_start[NSEG + 1];
// Packed interleaved fp16 tables: per token, 512B record =
//   [128 fp16 key row | 128 fp16 value row] = 32 uint4 (lane l owns uint4 l).
// Total: 32000 * 512B = 16.4 MB.
__device__ __align__(16) uint4 g_pack[VOCAB * 32];

// ---------------------------------------------------------------------------
// Kernel 0: convert both f32 tables into the packed fp16 layout.
// One thread per output uint4 (1,024,000 threads): 2 float4 reads, 1 uint4
// write. Lanes 0-15 of each record come from C_hop, 16-31 from C_hop1.
// ---------------------------------------------------------------------------
__global__ void __launch_bounds__(256)
convert_kernel(const float4* __restrict__ C_hop,
               const float4* __restrict__ C_hop1) {
    const int NT = VOCAB * 32;                 // 1,024,000 output uint4s
    int j = blockIdx.x * blockDim.x + threadIdx.x;
    if (j >= NT) return;
    const int r = j >> 5;                      // token row
    const int c = j & 31;                      // uint4 slot in 512B record

    const float4* src = (c < 16) ? C_hop : C_hop1;
    const int cc = c & 15;

    float4 a0 = __ldg(&src[r * 32 + 2 * cc]);
    float4 a1 = __ldg(&src[r * 32 + 2 * cc + 1]);

    union { __half2 h2[4]; uint4 u; } p;
    p.h2[0] = __floats2half2_rn(a0.x, a0.y);
    p.h2[1] = __floats2half2_rn(a0.z, a0.w);
    p.h2[2] = __floats2half2_rn(a1.x, a1.y);
    p.h2[3] = __floats2half2_rn(a1.z, a1.w);

    g_pack[j] = p.u;
}

// ---------------------------------------------------------------------------
// Kernel 1: binary-search segment boundaries in the sorted tree_ids array.
// ---------------------------------------------------------------------------
__global__ void seg_bounds_kernel(const int* __restrict__ tree_ids, int n) {
    int s = blockIdx.x * blockDim.x + threadIdx.x;
    if (s > NSEG) return;
    int lo = 0, hi = n;
    while (lo < hi) {
        int mid = (lo + hi) >> 1;
        if (__ldg(&tree_ids[mid]) < s) lo = mid + 1;
        else hi = mid;
    }
    g_seg_start[s] = lo;
}

// ---------------------------------------------------------------------------
// Kernel 2: ONE warp per segment. One 512B warp load per token fetches BOTH
// tables (lanes 0-15: key row, lanes 16-31: value row; uint4 = 8 fp16).
// Main loop AND remainder both keep 4 independent loads in flight.
// ---------------------------------------------------------------------------
__device__ __forceinline__ void acc8(float4& sa, float4& sb, uint4 r) {
    union { uint4 u; __half2 h[4]; } c; c.u = r;
    float2 f;
    f = __half22float2(c.h[0]); sa.x += f.x; sa.y += f.y;
    f = __half22float2(c.h[1]); sa.z += f.x; sa.w += f.y;
    f = __half22float2(c.h[2]); sb.x += f.x; sb.y += f.y;
    f = __half22float2(c.h[3]); sb.z += f.x; sb.w += f.y;
}

__global__ void __launch_bounds__(256)
seg_sum_kernel(const int* __restrict__ token_ids,
               float4*    __restrict__ out)        // [2][NSEG][32] float4
{
    const int seg  = (blockIdx.x * blockDim.x + threadIdx.x) >> 5;
    const int lane = threadIdx.x & 31;
    if (seg >= NSEG) return;

    const int beg = g_seg_start[seg];
    const int end = g_seg_start[seg + 1];

    float4 s0a = make_float4(0.f,0.f,0.f,0.f), s0b = make_float4(0.f,0.f,0.f,0.f);
    float4 s1a = make_float4(0.f,0.f,0.f,0.f), s1b = make_float4(0.f,0.f,0.f,0.f);

    int base = beg;
    for (; base + 32 <= end; base += 32) {
        const int myid = __ldg(&token_ids[base + lane]);
        #pragma unroll
        for (int u = 0; u < 32; u += 4) {
            int t0 = __shfl_sync(0xffffffffu, myid, u + 0);
            int t1 = __shfl_sync(0xffffffffu, myid, u + 1);
            int t2 = __shfl_sync(0xffffffffu, myid, u + 2);
            int t3 = __shfl_sync(0xffffffffu, myid, u + 3);
            uint4 r0 = __ldcg(&g_pack[t0 * 32 + lane]);
            uint4 r1 = __ldcg(&g_pack[t1 * 32 + lane]);
            uint4 r2 = __ldcg(&g_pack[t2 * 32 + lane]);
            uint4 r3 = __ldcg(&g_pack[t3 * 32 + lane]);
            acc8(s0a, s0b, r0);
            acc8(s1a, s1b, r1);
            acc8(s0a, s0b, r2);
            acc8(s1a, s1b, r3);
        }
    }
    // Remainder (< 32 tokens): keep 4 loads in flight for the bulk of it.
    if (base < end) {
        const int rem  = end - base;
        const int myid = (lane < rem) ? __ldg(&token_ids[base + lane]) : 0;
        int u = 0;
        for (; u + 4 <= rem; u += 4) {
            int t0 = __shfl_sync(0xffffffffu, myid, u + 0);
            int t1 = __shfl_sync(0xffffffffu, myid, u + 1);
            int t2 = __shfl_sync(0xffffffffu, myid, u + 2);
            int t3 = __shfl_sync(0xffffffffu, myid, u + 3);
            uint4 r0 = __ldcg(&g_pack[t0 * 32 + lane]);
            uint4 r1 = __ldcg(&g_pack[t1 * 32 + lane]);
            uint4 r2 = __ldcg(&g_pack[t2 * 32 + lane]);
            uint4 r3 = __ldcg(&g_pack[t3 * 32 + lane]);
            acc8(s0a, s0b, r0);
            acc8(s1a, s1b, r1);
            acc8(s0a, s0b, r2);
            acc8(s1a, s1b, r3);
        }
        for (; u < rem; u++) {
            int t = __shfl_sync(0xffffffffu, myid, u);
            uint4 r = __ldcg(&g_pack[t * 32 + lane]);
            acc8(s0a, s0b, r);
        }
    }

    s0a.x += s1a.x; s0a.y += s1a.y; s0a.z += s1a.z; s0a.w += s1a.w;
    s0b.x += s1b.x; s0b.y += s1b.y; s0b.z += s1b.z; s0b.w += s1b.w;

    // lanes 0-15 hold key-row floats [8c..8c+8); lanes 16-31 value-row.
    const int tbl = lane >> 4;          // 0 = key, 1 = value
    const int col = lane & 15;          // float4-pair index within the row
    float4* dst = &out[(((size_t)tbl * NSEG) + seg) * 32 + col * 2];
    dst[0] = s0a;
    dst[1] = s0b;
}

// ---------------------------------------------------------------------------
// Launch
// ---------------------------------------------------------------------------
extern "C" void kernel_launch(void* const* d_in, const int* in_sizes, int n_in,
                              void* d_out, int out_size) {
    const int*    token_ids = (const int*)   d_in[0];
    const int*    tree_ids  = (const int*)   d_in[1];
    const float4* C_hop     = (const float4*)d_in[2];
    const float4* C_hop1    = (const float4*)d_in[3];
    float4*       out       = (float4*)      d_out;

    const int n = in_sizes[0];  // TOTAL_TOKENS

    // Kernel 0: f32 -> packed fp16 conversion (1,024,000 threads)
    {
        int threads = 256;
        int blocks  = (VOCAB * 32 + threads - 1) / threads;   // 4000
        convert_kernel<<<blocks, threads>>>(C_hop, C_hop1);
    }

    // Kernel 1: segment boundaries (16385 binary searches)
    {
        int threads = 256;
        int blocks  = (NSEG + 1 + threads - 1) / threads;
        seg_bounds_kernel<<<blocks, threads>>>(tree_ids, n);
    }

    // Kernel 2: one warp per segment -> 16384 warps = 2048 blocks
    {
        int threads = 256;
        int blocks  = (NSEG * 32 + threads - 1) / threads;    // 2048
        seg_sum_kernel<<<blocks, threads>>>(token_ids, out);
    }
}